// round 3
// baseline (speedup 1.0000x reference)
#include <cuda_runtime.h>

#define NN 65536
#define NE 1048576
#define DD 64
#define NL 12
#define NM 2

// ---- device scratch (static allocation only, per harness rules) ----
__device__ float g_buf[NN * DD];      // ping buffer: conv output / next-layer input
__device__ float g_hw[NN * DD];       // hw = act(h) @ W
__device__ float g_dinv[NN];
__device__ int   g_deg[NN];
__device__ int   g_rowstart[NN + 1];
__device__ int   g_cursor[NN];
__device__ int2  g_csr[NE];           // {src, bitcast(dinv[src])}

// ---------------- CSR build ----------------
__global__ void k_zero_deg() {
    int i = blockIdx.x * blockDim.x + threadIdx.x;
    if (i < NN) g_deg[i] = 0;
}

__global__ void k_count(const int* __restrict__ dst) {
    int e = blockIdx.x * blockDim.x + threadIdx.x;
    if (e < NE) atomicAdd(&g_deg[dst[e] & (NN - 1)], 1);
}

__global__ void k_dinv() {
    int i = blockIdx.x * blockDim.x + threadIdx.x;
    if (i < NN) g_dinv[i] = rsqrtf((float)g_deg[i] + 1.0f);
}

// single-block exclusive scan of g_deg -> g_rowstart (+ cursor copy)
__global__ void k_scan() {
    __shared__ int part[1024];
    int t = threadIdx.x;
    int base = t * 64;
    int s = 0;
    for (int k = 0; k < 64; k++) s += g_deg[base + k];
    part[t] = s;
    __syncthreads();
    for (int off = 1; off < 1024; off <<= 1) {
        int v = (t >= off) ? part[t - off] : 0;
        __syncthreads();
        part[t] += v;
        __syncthreads();
    }
    int off = part[t] - s;  // exclusive base for this thread's chunk
    for (int k = 0; k < 64; k++) {
        g_rowstart[base + k] = off;
        g_cursor[base + k] = off;
        off += g_deg[base + k];
    }
    if (t == 1023) g_rowstart[NN] = off;
}

__global__ void k_fill(const int* __restrict__ src,
                       const int* __restrict__ dst) {
    int e = blockIdx.x * blockDim.x + threadIdx.x;
    if (e < NE) {
        int s = src[e] & (NN - 1);
        int d = dst[e] & (NN - 1);
        int pos = atomicAdd(&g_cursor[d], 1);
        g_csr[pos] = make_int2(s, __float_as_int(g_dinv[s]));
    }
}

// ---------------- GEMM: hw = act(A) @ W  (A: [NN,64], W: [64,64]) ----------------
// 256 threads, 64-row tile per block, 4x4 micro-tile per thread. ReLU fused on A load.
__global__ __launch_bounds__(256) void k_gemm(const float* __restrict__ A,
                                              const float* __restrict__ W,
                                              float* __restrict__ out,
                                              int relu) {
    __shared__ float As[64 * 64];
    __shared__ float Ws[64 * 64];
    int tid = threadIdx.x;

    const float4* A4 = (const float4*)(A + (size_t)blockIdx.x * 64 * DD);
    const float4* W4 = (const float4*)W;
    float4* As4 = (float4*)As;
    float4* Ws4 = (float4*)Ws;
#pragma unroll
    for (int k = 0; k < 4; k++) {
        float4 a = A4[tid + k * 256];
        if (relu) {
            a.x = fmaxf(a.x, 0.f); a.y = fmaxf(a.y, 0.f);
            a.z = fmaxf(a.z, 0.f); a.w = fmaxf(a.w, 0.f);
        }
        As4[tid + k * 256] = a;
        Ws4[tid + k * 256] = W4[tid + k * 256];
    }
    __syncthreads();

    int tx = tid & 15;   // col group
    int ty = tid >> 4;   // row group
    float acc[4][4];
#pragma unroll
    for (int m = 0; m < 4; m++)
#pragma unroll
        for (int n = 0; n < 4; n++) acc[m][n] = 0.f;

#pragma unroll
    for (int k = 0; k < 64; k++) {
        float4 w = *(const float4*)&Ws[k * 64 + tx * 4];
        float a0 = As[(ty * 4 + 0) * 64 + k];
        float a1 = As[(ty * 4 + 1) * 64 + k];
        float a2 = As[(ty * 4 + 2) * 64 + k];
        float a3 = As[(ty * 4 + 3) * 64 + k];
        acc[0][0] += a0 * w.x; acc[0][1] += a0 * w.y; acc[0][2] += a0 * w.z; acc[0][3] += a0 * w.w;
        acc[1][0] += a1 * w.x; acc[1][1] += a1 * w.y; acc[1][2] += a1 * w.z; acc[1][3] += a1 * w.w;
        acc[2][0] += a2 * w.x; acc[2][1] += a2 * w.y; acc[2][2] += a2 * w.z; acc[2][3] += a2 * w.w;
        acc[3][0] += a3 * w.x; acc[3][1] += a3 * w.y; acc[3][2] += a3 * w.z; acc[3][3] += a3 * w.w;
    }

    float4* O4 = (float4*)(out + (size_t)blockIdx.x * 64 * DD);
#pragma unroll
    for (int m = 0; m < 4; m++) {
        float4 r = make_float4(acc[m][0], acc[m][1], acc[m][2], acc[m][3]);
        O4[(ty * 4 + m) * 16 + tx] = r;
    }
}

// ---------------- AGG: out[n] = dinv[n]*sum_e dinv[src]*hw[src] + dinv[n]^2*hw[n] + b ----------------
// 16 threads per node, float4 lanes. Pure gather, no atomics.
__global__ __launch_bounds__(128) void k_agg(const float* __restrict__ hw,
                                             const float* __restrict__ b,
                                             float* __restrict__ out) {
    int t = threadIdx.x & 15;
    int nl = threadIdx.x >> 4;
    int n = blockIdx.x * 8 + nl;

    int beg = g_rowstart[n];
    int end = g_rowstart[n + 1];

    const float4* hw4 = (const float4*)hw;
    float4 acc = make_float4(0.f, 0.f, 0.f, 0.f);

    int e = beg;
    // 2-edge unrolled main loop for load-level parallelism
    for (; e + 1 < end; e += 2) {
        int2 sw0 = g_csr[e];
        int2 sw1 = g_csr[e + 1];
        float4 v0 = hw4[(size_t)sw0.x * 16 + t];
        float4 v1 = hw4[(size_t)sw1.x * 16 + t];
        float w0 = __int_as_float(sw0.y);
        float w1 = __int_as_float(sw1.y);
        acc.x += w0 * v0.x; acc.y += w0 * v0.y; acc.z += w0 * v0.z; acc.w += w0 * v0.w;
        acc.x += w1 * v1.x; acc.y += w1 * v1.y; acc.z += w1 * v1.z; acc.w += w1 * v1.w;
    }
    if (e < end) {
        int2 sw = g_csr[e];
        float w = __int_as_float(sw.y);
        float4 v = hw4[(size_t)sw.x * 16 + t];
        acc.x += w * v.x; acc.y += w * v.y; acc.z += w * v.z; acc.w += w * v.w;
    }

    float di = g_dinv[n];
    float d2 = di * di;
    float4 self = hw4[(size_t)n * 16 + t];
    float4 bb = ((const float4*)b)[t];
    float4 r;
    r.x = di * acc.x + d2 * self.x + bb.x;
    r.y = di * acc.y + d2 * self.y + bb.y;
    r.z = di * acc.z + d2 * self.z + bb.z;
    r.w = di * acc.w + d2 * self.w + bb.w;
    ((float4*)out)[(size_t)n * 16 + t] = r;
}

// ---------------- launcher ----------------
extern "C" void kernel_launch(void* const* d_in, const int* in_sizes, int n_in,
                              void* d_out, int out_size) {
    const float* x  = (const float*)d_in[0];
    const int*   ei = (const int*)d_in[1];   // int32: JAX demotes int64 with x64 disabled
    const float* W  = (const float*)d_in[2];
    const float* b  = (const float*)d_in[3];
    float*       out = (float*)d_out;

    float *pbuf, *phw;
    cudaGetSymbolAddress((void**)&pbuf, g_buf);
    cudaGetSymbolAddress((void**)&phw, g_hw);

    for (int i = 0; i < NM; i++) {
        const int* src = ei + (size_t)i * 2 * NE;
        const int* dst = src + NE;

        k_zero_deg<<<NN / 256, 256>>>();
        k_count<<<NE / 256, 256>>>(dst);
        k_dinv<<<NN / 256, 256>>>();
        k_scan<<<1, 1024>>>();
        k_fill<<<NE / 256, 256>>>(src, dst);

        const float* hin = x + (size_t)i * NN * DD;
        for (int j = 0; j < NL; j++) {
            const float* Wj = W + ((size_t)i * NL + j) * DD * DD;
            const float* bj = b + ((size_t)i * NL + j) * DD;
            const float* in = (j == 0) ? hin : (const float*)pbuf;
            float* outp = (j == NL - 1) ? (out + (size_t)i * NN * DD) : pbuf;

            k_gemm<<<NN / 64, 256>>>(in, Wj, phw, (j == 0) ? 0 : 1);
            k_agg<<<NN / 8, 128>>>(phw, bj, outp);
        }
    }
}

// round 4
// speedup vs baseline: 1.0019x; 1.0019x over previous
#include <cuda_runtime.h>

#define NN 65536
#define NE 1048576
#define DD 64
#define NL 12
#define NM 2

// ---- device scratch (static allocation only, per harness rules) ----
__device__ float g_buf[NN * DD];      // ping buffer: conv output / next-layer input
__device__ float g_hw[NN * DD];       // hw = act(h) @ W
__device__ float g_dinv[NN];
__device__ int   g_deg[NN];
__device__ int   g_rowstart[NN + 1];
__device__ int   g_cursor[NN];
__device__ int2  g_csr[NE];           // {src, bitcast(dinv[src])}

// ---------------- CSR build ----------------
__global__ void k_zero_deg() {
    int i = blockIdx.x * blockDim.x + threadIdx.x;
    if (i < NN) g_deg[i] = 0;
}

__global__ void k_count(const int* __restrict__ dst) {
    int e = blockIdx.x * blockDim.x + threadIdx.x;
    if (e < NE) atomicAdd(&g_deg[dst[e] & (NN - 1)], 1);
}

__global__ void k_dinv() {
    int i = blockIdx.x * blockDim.x + threadIdx.x;
    if (i < NN) g_dinv[i] = rsqrtf((float)g_deg[i] + 1.0f);
}

// single-block exclusive scan of g_deg -> g_rowstart (+ cursor copy)
__global__ void k_scan() {
    __shared__ int part[1024];
    int t = threadIdx.x;
    int base = t * 64;
    int s = 0;
    for (int k = 0; k < 64; k++) s += g_deg[base + k];
    part[t] = s;
    __syncthreads();
    for (int off = 1; off < 1024; off <<= 1) {
        int v = (t >= off) ? part[t - off] : 0;
        __syncthreads();
        part[t] += v;
        __syncthreads();
    }
    int off = part[t] - s;  // exclusive base for this thread's chunk
    for (int k = 0; k < 64; k++) {
        g_rowstart[base + k] = off;
        g_cursor[base + k] = off;
        off += g_deg[base + k];
    }
    if (t == 1023) g_rowstart[NN] = off;
}

__global__ void k_fill(const int* __restrict__ src,
                       const int* __restrict__ dst) {
    int e = blockIdx.x * blockDim.x + threadIdx.x;
    if (e < NE) {
        int s = src[e] & (NN - 1);
        int d = dst[e] & (NN - 1);
        int pos = atomicAdd(&g_cursor[d], 1);
        g_csr[pos] = make_int2(s, __float_as_int(g_dinv[s]));
    }
}

// ---------------- GEMM: hw = act(A) @ W  (A: [NN,64], W: [64,64]) ----------------
// 256 threads, 64-row tile per block, 4x4 micro-tile per thread. ReLU fused on A load.
__global__ __launch_bounds__(256) void k_gemm(const float* __restrict__ A,
                                              const float* __restrict__ W,
                                              float* __restrict__ out,
                                              int relu) {
    __shared__ float As[64 * 64];
    __shared__ float Ws[64 * 64];
    int tid = threadIdx.x;

    const float4* A4 = (const float4*)(A + (size_t)blockIdx.x * 64 * DD);
    const float4* W4 = (const float4*)W;
    float4* As4 = (float4*)As;
    float4* Ws4 = (float4*)Ws;
#pragma unroll
    for (int k = 0; k < 4; k++) {
        float4 a = A4[tid + k * 256];
        if (relu) {
            a.x = fmaxf(a.x, 0.f); a.y = fmaxf(a.y, 0.f);
            a.z = fmaxf(a.z, 0.f); a.w = fmaxf(a.w, 0.f);
        }
        As4[tid + k * 256] = a;
        Ws4[tid + k * 256] = W4[tid + k * 256];
    }
    __syncthreads();

    int tx = tid & 15;   // col group
    int ty = tid >> 4;   // row group
    float acc[4][4];
#pragma unroll
    for (int m = 0; m < 4; m++)
#pragma unroll
        for (int n = 0; n < 4; n++) acc[m][n] = 0.f;

#pragma unroll
    for (int k = 0; k < 64; k++) {
        float4 w = *(const float4*)&Ws[k * 64 + tx * 4];
        float a0 = As[(ty * 4 + 0) * 64 + k];
        float a1 = As[(ty * 4 + 1) * 64 + k];
        float a2 = As[(ty * 4 + 2) * 64 + k];
        float a3 = As[(ty * 4 + 3) * 64 + k];
        acc[0][0] += a0 * w.x; acc[0][1] += a0 * w.y; acc[0][2] += a0 * w.z; acc[0][3] += a0 * w.w;
        acc[1][0] += a1 * w.x; acc[1][1] += a1 * w.y; acc[1][2] += a1 * w.z; acc[1][3] += a1 * w.w;
        acc[2][0] += a2 * w.x; acc[2][1] += a2 * w.y; acc[2][2] += a2 * w.z; acc[2][3] += a2 * w.w;
        acc[3][0] += a3 * w.x; acc[3][1] += a3 * w.y; acc[3][2] += a3 * w.z; acc[3][3] += a3 * w.w;
    }

    float4* O4 = (float4*)(out + (size_t)blockIdx.x * 64 * DD);
#pragma unroll
    for (int m = 0; m < 4; m++) {
        float4 r = make_float4(acc[m][0], acc[m][1], acc[m][2], acc[m][3]);
        O4[(ty * 4 + m) * 16 + tx] = r;
    }
}

// ---------------- AGG: out[n] = dinv[n]*sum_e dinv[src]*hw[src] + dinv[n]^2*hw[n] + b ----------------
// 16 threads per node, float4 lanes. Pure gather, no atomics.
__global__ __launch_bounds__(128) void k_agg(const float* __restrict__ hw,
                                             const float* __restrict__ b,
                                             float* __restrict__ out) {
    int t = threadIdx.x & 15;
    int nl = threadIdx.x >> 4;
    int n = blockIdx.x * 8 + nl;

    int beg = g_rowstart[n];
    int end = g_rowstart[n + 1];

    const float4* hw4 = (const float4*)hw;
    float4 acc = make_float4(0.f, 0.f, 0.f, 0.f);

    int e = beg;
    // 2-edge unrolled main loop for load-level parallelism
    for (; e + 1 < end; e += 2) {
        int2 sw0 = g_csr[e];
        int2 sw1 = g_csr[e + 1];
        float4 v0 = hw4[(size_t)sw0.x * 16 + t];
        float4 v1 = hw4[(size_t)sw1.x * 16 + t];
        float w0 = __int_as_float(sw0.y);
        float w1 = __int_as_float(sw1.y);
        acc.x += w0 * v0.x; acc.y += w0 * v0.y; acc.z += w0 * v0.z; acc.w += w0 * v0.w;
        acc.x += w1 * v1.x; acc.y += w1 * v1.y; acc.z += w1 * v1.z; acc.w += w1 * v1.w;
    }
    if (e < end) {
        int2 sw = g_csr[e];
        float w = __int_as_float(sw.y);
        float4 v = hw4[(size_t)sw.x * 16 + t];
        acc.x += w * v.x; acc.y += w * v.y; acc.z += w * v.z; acc.w += w * v.w;
    }

    float di = g_dinv[n];
    float d2 = di * di;
    float4 self = hw4[(size_t)n * 16 + t];
    float4 bb = ((const float4*)b)[t];
    float4 r;
    r.x = di * acc.x + d2 * self.x + bb.x;
    r.y = di * acc.y + d2 * self.y + bb.y;
    r.z = di * acc.z + d2 * self.z + bb.z;
    r.w = di * acc.w + d2 * self.w + bb.w;
    ((float4*)out)[(size_t)n * 16 + t] = r;
}

// ---------------- launcher ----------------
extern "C" void kernel_launch(void* const* d_in, const int* in_sizes, int n_in,
                              void* d_out, int out_size) {
    const float* x  = (const float*)d_in[0];
    const int*   ei = (const int*)d_in[1];   // int32: JAX demotes int64 with x64 disabled
    const float* W  = (const float*)d_in[2];
    const float* b  = (const float*)d_in[3];
    float*       out = (float*)d_out;

    float *pbuf, *phw;
    cudaGetSymbolAddress((void**)&pbuf, g_buf);
    cudaGetSymbolAddress((void**)&phw, g_hw);

    for (int i = 0; i < NM; i++) {
        const int* src = ei + (size_t)i * 2 * NE;
        const int* dst = src + NE;

        k_zero_deg<<<NN / 256, 256>>>();
        k_count<<<NE / 256, 256>>>(dst);
        k_dinv<<<NN / 256, 256>>>();
        k_scan<<<1, 1024>>>();
        k_fill<<<NE / 256, 256>>>(src, dst);

        const float* hin = x + (size_t)i * NN * DD;
        for (int j = 0; j < NL; j++) {
            const float* Wj = W + ((size_t)i * NL + j) * DD * DD;
            const float* bj = b + ((size_t)i * NL + j) * DD;
            const float* in = (j == 0) ? hin : (const float*)pbuf;
            float* outp = (j == NL - 1) ? (out + (size_t)i * NN * DD) : pbuf;

            k_gemm<<<NN / 64, 256>>>(in, Wj, phw, (j == 0) ? 0 : 1);
            k_agg<<<NN / 8, 128>>>(phw, bj, outp);
        }
    }
}